// round 16
// baseline (speedup 1.0000x reference)
#include <cuda_runtime.h>
#include <cuda_fp16.h>
#include <cstdint>

// ---------------------------------------------------------------------------
// TSABlock — fp16 mma.sync GEMMs (Round 13)
//   temb/y/out: R8-exact (BM=BN=128, 128 thr, 2 CTA/SM)
//   qkv:        wide variant (BM=128, BN=256, 256 thr, 1 CTA/SM)
// ---------------------------------------------------------------------------

#define N_ROWS   65536
#define N_BATCH  8192
#define IN_CH    1024
#define OUT_CH   512
#define T_DIM    512
#define QKV_CH   1536

#define BM 128
#define BN 128
#define BK 64
static constexpr int A_BYTES = BM * 128;                // 16 KB
static constexpr int B_BYTES = BN * 128;                // 16 KB
static constexpr int STAGE_BYTES = A_BYTES + B_BYTES;   // 32 KB
static constexpr int NSTAGE = 3;
static constexpr int SMEM_BYTES = NSTAGE * STAGE_BYTES; // 96 KB

// wide (qkv) config
#define BN2 256
static constexpr int B2_BYTES = BN2 * 128;                 // 32 KB
static constexpr int STAGE2_BYTES = A_BYTES + B2_BYTES;    // 48 KB
static constexpr int SMEM2_BYTES = NSTAGE * STAGE2_BYTES;  // 144 KB

// ------------------------- device scratch (no cudaMalloc) -------------------
__device__ __align__(16) __half g_xh  [N_ROWS * IN_CH];
__device__ __align__(16) __half g_th  [N_BATCH * T_DIM];
__device__ __align__(16) __half g_Wdh [OUT_CH * IN_CH];
__device__ __align__(16) __half g_Wth [OUT_CH * T_DIM];
__device__ __align__(16) __half g_Wqh [QKV_CH * OUT_CH];
__device__ __align__(16) __half g_Woh [OUT_CH * OUT_CH];
__device__ __align__(16) float  g_temb[N_BATCH * OUT_CH];
__device__ __align__(16) __half g_yh  [N_ROWS * OUT_CH];
__device__ __align__(16) __half g_qkvh[N_ROWS * QKV_CH];
__device__ __align__(16) __half g_ath [N_ROWS * OUT_CH];

// ------------------------------ PTX helpers --------------------------------
__device__ __forceinline__ uint32_t smem_u32(const void* p) {
    uint32_t a;
    asm("{ .reg .u64 t; cvta.to.shared.u64 t, %1; cvt.u32.u64 %0, t; }"
        : "=r"(a) : "l"(p));
    return a;
}
#define CP_COMMIT() asm volatile("cp.async.commit_group;" ::: "memory")
#define CP_WAIT1()  asm volatile("cp.async.wait_group 1;" ::: "memory")

__device__ __forceinline__ void cp16(uint32_t dst, const void* src) {
    asm volatile("cp.async.cg.shared.global [%0], [%1], 16;" :: "r"(dst), "l"(src));
}

__device__ __forceinline__ void ldsm_x4(uint32_t& r0, uint32_t& r1,
                                        uint32_t& r2, uint32_t& r3, uint32_t a) {
    asm volatile("ldmatrix.sync.aligned.m8n8.x4.shared.b16 {%0,%1,%2,%3}, [%4];"
                 : "=r"(r0), "=r"(r1), "=r"(r2), "=r"(r3) : "r"(a));
}

__device__ __forceinline__ void mma16816(float* d, const uint32_t* a, const uint32_t* b) {
    asm volatile(
        "mma.sync.aligned.m16n8k16.row.col.f32.f16.f16.f32 "
        "{%0,%1,%2,%3}, {%4,%5,%6,%7}, {%8,%9}, {%0,%1,%2,%3};"
        : "+f"(d[0]), "+f"(d[1]), "+f"(d[2]), "+f"(d[3])
        : "r"(a[0]), "r"(a[1]), "r"(a[2]), "r"(a[3]), "r"(b[0]), "r"(b[1]));
}

// ------------------------- GEMM kernel (R8-exact) --------------------------
// 128 threads, 4 warps 2x2, warp tile 64x64, BK=64, 3-stage cp.async.
// MODE 0: Cf = acc + bias
// MODE 1: Ch = half(acc + bias + temb[m>>3])
// MODE 2: Ch = half(acc + bias)
template<int MODE>
__global__ __launch_bounds__(128, 2)
void gemm_mma(const __half* __restrict__ Ah, const __half* __restrict__ Bh,
              const float* __restrict__ bias, const float* __restrict__ temb,
              float* __restrict__ Cf, __half* __restrict__ Ch,
              int M, int N, int K)
{
    extern __shared__ __align__(128) char smem[];
    const uint32_t sb = smem_u32(smem);

    const int tid  = threadIdx.x;
    const int wid  = tid >> 5;
    const int lane = tid & 31;
    const int warp_m = wid & 1;
    const int warp_n = wid >> 1;
    const int m0 = blockIdx.y * BM;
    const int n0 = blockIdx.x * BN;

    const int cpc = tid & 7;
    const int cpr = tid >> 3;
    const __half* gA = Ah + (size_t)(m0 + cpr) * K + cpc * 8;
    const __half* gB = Bh + (size_t)(n0 + cpr) * K + cpc * 8;
    const size_t rowstep = (size_t)16 * K;
    const uint32_t swz = cpr * 128 + ((cpc ^ (cpr & 7)) << 4);

    float acc[4][8][4];
#pragma unroll
    for (int a = 0; a < 4; a++)
#pragma unroll
        for (int b = 0; b < 8; b++)
#pragma unroll
            for (int c = 0; c < 4; c++) acc[a][b][c] = 0.0f;

    const int KT = K / BK;

    const int lr = lane & 15;
    const int lc = lane >> 4;
    uint32_t aBase[4], bBase[4];
#pragma unroll
    for (int f = 0; f < 4; f++) {
        const int ra = warp_m * 64 + f * 16 + lr;
        const int rb = warp_n * 64 + f * 16 + lr;
        aBase[f] = ra * 128 + ((((ra & 7) ^ lc)) << 4);
        bBase[f] = A_BYTES + rb * 128 + ((((rb & 7) ^ lc)) << 4);
    }

#pragma unroll
    for (int s = 0; s < 2; s++) {
        const uint32_t st = sb + s * STAGE_BYTES;
        const size_t k0 = (size_t)s * BK;
#pragma unroll
        for (int j = 0; j < 8; j++) {
            cp16(st + swz + j * 2048, gA + j * rowstep + k0);
            cp16(st + A_BYTES + swz + j * 2048, gB + j * rowstep + k0);
        }
        CP_COMMIT();
    }
    CP_WAIT1();
    __syncthreads();

    uint32_t aF[2][4][4], bF[2][8][2];

#pragma unroll
    for (int p = 0; p < 4; p++) {
        uint32_t r0, r1, r2, r3;
        ldsm_x4(r0, r1, r2, r3, sb + bBase[p]);
        bF[0][2 * p][0] = r0; bF[0][2 * p][1] = r2;
        bF[0][2 * p + 1][0] = r1; bF[0][2 * p + 1][1] = r3;
    }
#pragma unroll
    for (int mf = 0; mf < 4; mf++)
        ldsm_x4(aF[0][mf][0], aF[0][mf][1], aF[0][mf][2], aF[0][mf][3],
                sb + aBase[mf]);

#pragma unroll 1
    for (int kt = 0; kt < KT; kt++) {
        const uint32_t st = sb + (kt % NSTAGE) * STAGE_BYTES;

        if (kt + 2 < KT) {
            const uint32_t sn = sb + ((kt + 2) % NSTAGE) * STAGE_BYTES;
            const size_t k2 = (size_t)(kt + 2) * BK;
#pragma unroll
            for (int j = 0; j < 8; j++) {
                cp16(sn + swz + j * 2048, gA + j * rowstep + k2);
                cp16(sn + A_BYTES + swz + j * 2048, gB + j * rowstep + k2);
            }
        }
        CP_COMMIT();

#pragma unroll
        for (int ks = 0; ks < 4; ks++) {
            const int cur = ks & 1;
            const int nxt = cur ^ 1;
            if (ks < 3) {
                const uint32_t x = (uint32_t)(ks + 1) << 5;
#pragma unroll
                for (int p = 0; p < 4; p++) {
                    uint32_t r0, r1, r2, r3;
                    ldsm_x4(r0, r1, r2, r3, st + (bBase[p] ^ x));
                    bF[nxt][2 * p][0] = r0; bF[nxt][2 * p][1] = r2;
                    bF[nxt][2 * p + 1][0] = r1; bF[nxt][2 * p + 1][1] = r3;
                }
#pragma unroll
                for (int mf = 0; mf < 4; mf++)
                    ldsm_x4(aF[nxt][mf][0], aF[nxt][mf][1],
                            aF[nxt][mf][2], aF[nxt][mf][3], st + (aBase[mf] ^ x));
            } else if (kt < KT - 1) {
                CP_WAIT1();
                __syncthreads();
                const uint32_t stn = sb + ((kt + 1) % NSTAGE) * STAGE_BYTES;
#pragma unroll
                for (int p = 0; p < 4; p++) {
                    uint32_t r0, r1, r2, r3;
                    ldsm_x4(r0, r1, r2, r3, stn + bBase[p]);
                    bF[nxt][2 * p][0] = r0; bF[nxt][2 * p][1] = r2;
                    bF[nxt][2 * p + 1][0] = r1; bF[nxt][2 * p + 1][1] = r3;
                }
#pragma unroll
                for (int mf = 0; mf < 4; mf++)
                    ldsm_x4(aF[nxt][mf][0], aF[nxt][mf][1],
                            aF[nxt][mf][2], aF[nxt][mf][3], stn + aBase[mf]);
            }
#pragma unroll
            for (int mf = 0; mf < 4; mf++)
#pragma unroll
                for (int nf = 0; nf < 8; nf++)
                    mma16816(acc[mf][nf], aF[cur][mf], bF[cur][nf]);
        }
    }

#pragma unroll
    for (int mf = 0; mf < 4; mf++)
#pragma unroll
        for (int nf = 0; nf < 8; nf++) {
            const int m = m0 + warp_m * 64 + mf * 16 + (lane >> 2);
            const int n = n0 + warp_n * 64 + nf * 8 + 2 * (lane & 3);
            const float* a = acc[mf][nf];
            const float b0 = bias[n], b1 = bias[n + 1];
            if (MODE == 0) {
                float2 v0 = make_float2(a[0] + b0, a[1] + b1);
                float2 v1 = make_float2(a[2] + b0, a[3] + b1);
                *reinterpret_cast<float2*>(Cf + (size_t)m * N + n) = v0;
                *reinterpret_cast<float2*>(Cf + (size_t)(m + 8) * N + n) = v1;
            } else if (MODE == 1) {
#pragma unroll
                for (int rr = 0; rr < 2; rr++) {
                    const int mm = m + rr * 8;
                    const float* tp = temb + (size_t)(mm >> 3) * OUT_CH + n;
                    const float v0 = a[rr * 2 + 0] + b0 + tp[0];
                    const float v1 = a[rr * 2 + 1] + b1 + tp[1];
                    *reinterpret_cast<__half2*>(Ch + (size_t)mm * N + n) =
                        __floats2half2_rn(v0, v1);
                }
            } else {
                *reinterpret_cast<__half2*>(Ch + (size_t)m * N + n) =
                    __floats2half2_rn(a[0] + b0, a[1] + b1);
                *reinterpret_cast<__half2*>(Ch + (size_t)(m + 8) * N + n) =
                    __floats2half2_rn(a[2] + b0, a[3] + b1);
            }
        }
}

// --------------------- wide GEMM (qkv): 256 thr, BN=256 --------------------
// 8 warps 2(M)x4(N), warp tile 64x64, BK=64, 3-stage, 1 CTA/SM.
__global__ __launch_bounds__(256, 1)
void gemm_wide(const __half* __restrict__ Ah, const __half* __restrict__ Bh,
               const float* __restrict__ bias, __half* __restrict__ Ch,
               int M, int N, int K)
{
    extern __shared__ __align__(128) char smem[];
    const uint32_t sb = smem_u32(smem);

    const int tid  = threadIdx.x;
    const int wid  = tid >> 5;
    const int lane = tid & 31;
    const int warp_m = wid & 1;        // 2 over M
    const int warp_n = wid >> 1;       // 4 over N (64 each)
    const int m0 = blockIdx.y * BM;
    const int n0 = blockIdx.x * BN2;

    const int cpc = tid & 7;           // 16B chunk 0..7
    const int cpr = tid >> 3;          // base row 0..31
    const __half* gA = Ah + (size_t)(m0 + cpr) * K + cpc * 8;
    const __half* gB = Bh + (size_t)(n0 + cpr) * K + cpc * 8;
    const size_t rowstep = (size_t)32 * K;   // 32 rows per j
    const uint32_t swz = cpr * 128 + ((cpc ^ (cpr & 7)) << 4);

    float acc[4][8][4];
#pragma unroll
    for (int a = 0; a < 4; a++)
#pragma unroll
        for (int b = 0; b < 8; b++)
#pragma unroll
            for (int c = 0; c < 4; c++) acc[a][b][c] = 0.0f;

    const int KT = K / BK;

    const int lr = lane & 15;
    const int lc = lane >> 4;
    uint32_t aBase[4], bBase[4];
#pragma unroll
    for (int f = 0; f < 4; f++) {
        const int ra = warp_m * 64 + f * 16 + lr;
        const int rb = warp_n * 64 + f * 16 + lr;
        aBase[f] = ra * 128 + ((((ra & 7) ^ lc)) << 4);
        bBase[f] = A_BYTES + rb * 128 + ((((rb & 7) ^ lc)) << 4);
    }

#pragma unroll
    for (int s = 0; s < 2; s++) {
        const uint32_t st = sb + s * STAGE2_BYTES;
        const size_t k0 = (size_t)s * BK;
#pragma unroll
        for (int j = 0; j < 4; j++)          // A: 128 rows
            cp16(st + swz + j * 4096, gA + j * rowstep + k0);
#pragma unroll
        for (int j = 0; j < 8; j++)          // B: 256 rows
            cp16(st + A_BYTES + swz + j * 4096, gB + j * rowstep + k0);
        CP_COMMIT();
    }
    CP_WAIT1();
    __syncthreads();

    uint32_t aF[2][4][4], bF[2][8][2];

#pragma unroll
    for (int p = 0; p < 4; p++) {
        uint32_t r0, r1, r2, r3;
        ldsm_x4(r0, r1, r2, r3, sb + bBase[p]);
        bF[0][2 * p][0] = r0; bF[0][2 * p][1] = r2;
        bF[0][2 * p + 1][0] = r1; bF[0][2 * p + 1][1] = r3;
    }
#pragma unroll
    for (int mf = 0; mf < 4; mf++)
        ldsm_x4(aF[0][mf][0], aF[0][mf][1], aF[0][mf][2], aF[0][mf][3],
                sb + aBase[mf]);

#pragma unroll 1
    for (int kt = 0; kt < KT; kt++) {
        const uint32_t st = sb + (kt % NSTAGE) * STAGE2_BYTES;

        if (kt + 2 < KT) {
            const uint32_t sn = sb + ((kt + 2) % NSTAGE) * STAGE2_BYTES;
            const size_t k2 = (size_t)(kt + 2) * BK;
#pragma unroll
            for (int j = 0; j < 4; j++)
                cp16(sn + swz + j * 4096, gA + j * rowstep + k2);
#pragma unroll
            for (int j = 0; j < 8; j++)
                cp16(sn + A_BYTES + swz + j * 4096, gB + j * rowstep + k2);
        }
        CP_COMMIT();

#pragma unroll
        for (int ks = 0; ks < 4; ks++) {
            const int cur = ks & 1;
            const int nxt = cur ^ 1;
            if (ks < 3) {
                const uint32_t x = (uint32_t)(ks + 1) << 5;
#pragma unroll
                for (int p = 0; p < 4; p++) {
                    uint32_t r0, r1, r2, r3;
                    ldsm_x4(r0, r1, r2, r3, st + (bBase[p] ^ x));
                    bF[nxt][2 * p][0] = r0; bF[nxt][2 * p][1] = r2;
                    bF[nxt][2 * p + 1][0] = r1; bF[nxt][2 * p + 1][1] = r3;
                }
#pragma unroll
                for (int mf = 0; mf < 4; mf++)
                    ldsm_x4(aF[nxt][mf][0], aF[nxt][mf][1],
                            aF[nxt][mf][2], aF[nxt][mf][3], st + (aBase[mf] ^ x));
            } else if (kt < KT - 1) {
                CP_WAIT1();
                __syncthreads();
                const uint32_t stn = sb + ((kt + 1) % NSTAGE) * STAGE2_BYTES;
#pragma unroll
                for (int p = 0; p < 4; p++) {
                    uint32_t r0, r1, r2, r3;
                    ldsm_x4(r0, r1, r2, r3, stn + bBase[p]);
                    bF[nxt][2 * p][0] = r0; bF[nxt][2 * p][1] = r2;
                    bF[nxt][2 * p + 1][0] = r1; bF[nxt][2 * p + 1][1] = r3;
                }
#pragma unroll
                for (int mf = 0; mf < 4; mf++)
                    ldsm_x4(aF[nxt][mf][0], aF[nxt][mf][1],
                            aF[nxt][mf][2], aF[nxt][mf][3], stn + aBase[mf]);
            }
#pragma unroll
            for (int mf = 0; mf < 4; mf++)
#pragma unroll
                for (int nf = 0; nf < 8; nf++)
                    mma16816(acc[mf][nf], aF[cur][mf], bF[cur][nf]);
        }
    }

    // epilogue: fp16 out (MODE 2 semantics)
#pragma unroll
    for (int mf = 0; mf < 4; mf++)
#pragma unroll
        for (int nf = 0; nf < 8; nf++) {
            const int m = m0 + warp_m * 64 + mf * 16 + (lane >> 2);
            const int n = n0 + warp_n * 64 + nf * 8 + 2 * (lane & 3);
            const float* a = acc[mf][nf];
            const float b0 = bias[n], b1 = bias[n + 1];
            *reinterpret_cast<__half2*>(Ch + (size_t)m * N + n) =
                __floats2half2_rn(a[0] + b0, a[1] + b1);
            *reinterpret_cast<__half2*>(Ch + (size_t)(m + 8) * N + n) =
                __floats2half2_rn(a[2] + b0, a[3] + b1);
        }
}

// --------------------------- conversions (one launch) ----------------------
__device__ __forceinline__ void cvt4s(const float* __restrict__ s,
                                      __half* __restrict__ h, int i)
{
    float4 v = *reinterpret_cast<const float4*>(s + i);
    __half2 a = __floats2half2_rn(v.x, v.y);
    __half2 b = __floats2half2_rn(v.z, v.w);
    *reinterpret_cast<uint2*>(h + i) =
        make_uint2(*reinterpret_cast<uint32_t*>(&a), *reinterpret_cast<uint32_t*>(&b));
}

static constexpr int SZ_X  = N_ROWS * IN_CH;
static constexpr int SZ_T  = N_BATCH * T_DIM;
static constexpr int SZ_WD = OUT_CH * IN_CH;
static constexpr int SZ_WT = OUT_CH * T_DIM;
static constexpr int SZ_WQ = QKV_CH * OUT_CH;
static constexpr int SZ_WO = OUT_CH * OUT_CH;
static constexpr int C0 = SZ_X,       C1 = C0 + SZ_T,  C2 = C1 + SZ_WD;
static constexpr int C3 = C2 + SZ_WT, C4 = C3 + SZ_WQ, C5 = C4 + SZ_WO;
static constexpr int CVT_BLOCKS = C5 / 4 / 256;

__global__ __launch_bounds__(256)
void cvt_all(const float* __restrict__ x,  const float* __restrict__ t,
             const float* __restrict__ Wd, const float* __restrict__ Wt,
             const float* __restrict__ Wq, const float* __restrict__ Wo,
             __half* __restrict__ xh,  __half* __restrict__ th,
             __half* __restrict__ Wdh, __half* __restrict__ Wth,
             __half* __restrict__ Wqh, __half* __restrict__ Woh)
{
    int i = (blockIdx.x * 256 + threadIdx.x) * 4;
    if (i < C0)      cvt4s(x,  xh,  i);
    else if (i < C1) cvt4s(t,  th,  i - C0);
    else if (i < C2) cvt4s(Wd, Wdh, i - C1);
    else if (i < C3) cvt4s(Wt, Wth, i - C2);
    else if (i < C4) cvt4s(Wq, Wqh, i - C3);
    else             cvt4s(Wo, Woh, i - C4);
}

// ------------------------------ attention ----------------------------------
__device__ __forceinline__ void unpack8(float* f, uint4 u) {
    const __half2* h = reinterpret_cast<const __half2*>(&u);
#pragma unroll
    for (int k = 0; k < 4; k++) {
        float2 v = __half22float2(h[k]);
        f[2 * k] = v.x; f[2 * k + 1] = v.y;
    }
}

__global__ __launch_bounds__(256)
void attn_kernel(const __half* __restrict__ qkv, __half* __restrict__ oh)
{
    __shared__ __half s[8 * 1728];
    const int tid = threadIdx.x;
    const size_t row0 = (size_t)blockIdx.x * 8;

    const uint4* src = reinterpret_cast<const uint4*>(qkv + row0 * QKV_CH);
    uint4* dst = reinterpret_cast<uint4*>(s);
#pragma unroll
    for (int it = 0; it < 6; it++) {
        int idx = tid + it * 256;
        int r = idx / 192, j = idx - r * 192;
        int grp = j >> 3, w8 = j & 7;
        dst[r * 216 + grp * 9 + w8] = src[idx];
    }
    __syncthreads();

    const int warp = tid >> 5;
    const int lane = tid & 31;
    const __half* qs = s + warp * 1728;
    const int i  = lane & 7;
    const int c0 = (lane >> 3) * 16;

    float qreg[16];
    {
        const __half* qp = qs + i * 72 + c0;
        unpack8(qreg,     *reinterpret_cast<const uint4*>(qp));
        unpack8(qreg + 8, *reinterpret_cast<const uint4*>(qp + 8));
    }

    float w[8];
#pragma unroll
    for (int j = 0; j < 8; j++) {
        const __half* kp = qs + (8 + j) * 72 + c0;
        float kr[16];
        unpack8(kr,     *reinterpret_cast<const uint4*>(kp));
        unpack8(kr + 8, *reinterpret_cast<const uint4*>(kp + 8));
        float acc = 0.0f;
#pragma unroll
        for (int c = 0; c < 16; c++) acc = fmaf(qreg[c], kr[c], acc);
        acc += __shfl_xor_sync(0xffffffffu, acc, 8);
        acc += __shfl_xor_sync(0xffffffffu, acc, 16);
        w[j] = acc * 0.125f;
    }

    float mx = w[0];
#pragma unroll
    for (int j = 1; j < 8; j++) mx = fmaxf(mx, w[j]);
    float sum = 0.0f;
#pragma unroll
    for (int j = 0; j < 8; j++) { w[j] = __expf(w[j] - mx); sum += w[j]; }
    const float inv = 1.0f / sum;

    float o[16];
#pragma unroll
    for (int c = 0; c < 16; c++) o[c] = 0.0f;
#pragma unroll
    for (int j = 0; j < 8; j++) {
        const __half* vp = qs + (16 + j) * 72 + c0;
        float vr[16];
        unpack8(vr,     *reinterpret_cast<const uint4*>(vp));
        unpack8(vr + 8, *reinterpret_cast<const uint4*>(vp + 8));
        const float wj = w[j];
#pragma unroll
        for (int c = 0; c < 16; c++) o[c] = fmaf(wj, vr[c], o[c]);
    }

    __half* op = oh + (row0 + warp) * (size_t)OUT_CH + i * 64 + c0;
    uint32_t pk[8];
#pragma unroll
    for (int p = 0; p < 8; p++) {
        __half2 h = __floats2half2_rn(o[2 * p] * inv, o[2 * p + 1] * inv);
        pk[p] = *reinterpret_cast<uint32_t*>(&h);
    }
    *reinterpret_cast<uint4*>(op)     = make_uint4(pk[0], pk[1], pk[2], pk[3]);
    *reinterpret_cast<uint4*>(op + 8) = make_uint4(pk[4], pk[5], pk[6], pk[7]);
}

// ---------------------------------------------------------------------------
extern "C" void kernel_launch(void* const* d_in, const int* in_sizes, int n_in,
                              void* d_out, int out_size)
{
    const float* x      = (const float*)d_in[0];
    const float* t      = (const float*)d_in[1];
    const float* W_down = (const float*)d_in[2];
    const float* b_down = (const float*)d_in[3];
    const float* W_t    = (const float*)d_in[4];
    const float* b_t    = (const float*)d_in[5];
    const float* W_qkv  = (const float*)d_in[6];
    const float* b_qkv  = (const float*)d_in[7];
    const float* W_out  = (const float*)d_in[8];
    const float* b_out  = (const float*)d_in[9];
    float* out = (float*)d_out;

    __half *xh, *th, *Wdh, *Wth, *Wqh, *Woh, *yh, *qkvh, *ath;
    float *temb;
    cudaGetSymbolAddress((void**)&xh,   g_xh);
    cudaGetSymbolAddress((void**)&th,   g_th);
    cudaGetSymbolAddress((void**)&Wdh,  g_Wdh);
    cudaGetSymbolAddress((void**)&Wth,  g_Wth);
    cudaGetSymbolAddress((void**)&Wqh,  g_Wqh);
    cudaGetSymbolAddress((void**)&Woh,  g_Woh);
    cudaGetSymbolAddress((void**)&temb, g_temb);
    cudaGetSymbolAddress((void**)&yh,   g_yh);
    cudaGetSymbolAddress((void**)&qkvh, g_qkvh);
    cudaGetSymbolAddress((void**)&ath,  g_ath);

    cudaFuncSetAttribute(gemm_mma<0>, cudaFuncAttributeMaxDynamicSharedMemorySize, SMEM_BYTES);
    cudaFuncSetAttribute(gemm_mma<1>, cudaFuncAttributeMaxDynamicSharedMemorySize, SMEM_BYTES);
    cudaFuncSetAttribute(gemm_wide,   cudaFuncAttributeMaxDynamicSharedMemorySize, SMEM2_BYTES);

    // launch 0: conversions
    cvt_all<<<CVT_BLOCKS, 256>>>(x, t, W_down, W_t, W_qkv, W_out,
                                 xh, th, Wdh, Wth, Wqh, Woh);

    // launch 1: temb = t @ W_t^T + b_t             [8192, 512] fp32
    gemm_mma<0><<<dim3(OUT_CH / BN, N_BATCH / BM), 128, SMEM_BYTES>>>(
        th, Wth, b_t, nullptr, temb, nullptr, N_BATCH, OUT_CH, T_DIM);

    // launch 2: y = x @ W_down^T + b_down + temb   -> fp16
    gemm_mma<1><<<dim3(OUT_CH / BN, N_ROWS / BM), 128, SMEM_BYTES>>>(
        xh, Wdh, b_down, temb, nullptr, yh, N_ROWS, OUT_CH, IN_CH);

    // launch 3: qkv = y @ W_qkv^T + b_qkv          -> fp16 (wide experiment)
    gemm_wide<<<dim3(QKV_CH / BN2, N_ROWS / BM), 256, SMEM2_BYTES>>>(
        yh, Wqh, b_qkv, qkvh, N_ROWS, QKV_CH, OUT_CH);

    // launch 4: att = rowwise attention(qkv)       -> fp16
    attn_kernel<<<N_ROWS / 8, 256>>>(qkvh, ath);

    // launch 5: out = att @ W_out^T + b_out (fp32)
    gemm_mma<0><<<dim3(OUT_CH / BN, N_ROWS / BM), 128, SMEM_BYTES>>>(
        ath, Woh, b_out, nullptr, out, nullptr, N_ROWS, OUT_CH, OUT_CH);
}

// round 17
// speedup vs baseline: 1.0463x; 1.0463x over previous
#include <cuda_runtime.h>
#include <cuda_fp16.h>
#include <cstdint>

// ---------------------------------------------------------------------------
// TSABlock — fp16 mma.sync GEMMs, BK=64, 3-stage cp.async (R8-exact config,
//            rotating stage pointers instead of %NSTAGE) (Round 14)
// ---------------------------------------------------------------------------

#define N_ROWS   65536
#define N_BATCH  8192
#define IN_CH    1024
#define OUT_CH   512
#define T_DIM    512
#define QKV_CH   1536

#define BM 128
#define BN 128
#define BK 64
static constexpr int A_BYTES = BM * 128;                // 16 KB
static constexpr int B_BYTES = BN * 128;                // 16 KB
static constexpr int STAGE_BYTES = A_BYTES + B_BYTES;   // 32 KB
static constexpr int NSTAGE = 3;
static constexpr int SMEM_BYTES = NSTAGE * STAGE_BYTES; // 96 KB -> 2 CTAs/SM

// ------------------------- device scratch (no cudaMalloc) -------------------
__device__ __align__(16) __half g_xh  [N_ROWS * IN_CH];
__device__ __align__(16) __half g_th  [N_BATCH * T_DIM];
__device__ __align__(16) __half g_Wdh [OUT_CH * IN_CH];
__device__ __align__(16) __half g_Wth [OUT_CH * T_DIM];
__device__ __align__(16) __half g_Wqh [QKV_CH * OUT_CH];
__device__ __align__(16) __half g_Woh [OUT_CH * OUT_CH];
__device__ __align__(16) float  g_temb[N_BATCH * OUT_CH];
__device__ __align__(16) __half g_yh  [N_ROWS * OUT_CH];
__device__ __align__(16) __half g_qkvh[N_ROWS * QKV_CH];
__device__ __align__(16) __half g_ath [N_ROWS * OUT_CH];

// ------------------------------ PTX helpers --------------------------------
__device__ __forceinline__ uint32_t smem_u32(const void* p) {
    uint32_t a;
    asm("{ .reg .u64 t; cvta.to.shared.u64 t, %1; cvt.u32.u64 %0, t; }"
        : "=r"(a) : "l"(p));
    return a;
}
#define CP_COMMIT() asm volatile("cp.async.commit_group;" ::: "memory")
#define CP_WAIT1()  asm volatile("cp.async.wait_group 1;" ::: "memory")

__device__ __forceinline__ void cp16(uint32_t dst, const void* src) {
    asm volatile("cp.async.cg.shared.global [%0], [%1], 16;" :: "r"(dst), "l"(src));
}

__device__ __forceinline__ void ldsm_x4(uint32_t& r0, uint32_t& r1,
                                        uint32_t& r2, uint32_t& r3, uint32_t a) {
    asm volatile("ldmatrix.sync.aligned.m8n8.x4.shared.b16 {%0,%1,%2,%3}, [%4];"
                 : "=r"(r0), "=r"(r1), "=r"(r2), "=r"(r3) : "r"(a));
}

__device__ __forceinline__ void mma16816(float* d, const uint32_t* a, const uint32_t* b) {
    asm volatile(
        "mma.sync.aligned.m16n8k16.row.col.f32.f16.f16.f32 "
        "{%0,%1,%2,%3}, {%4,%5,%6,%7}, {%8,%9}, {%0,%1,%2,%3};"
        : "+f"(d[0]), "+f"(d[1]), "+f"(d[2]), "+f"(d[3])
        : "r"(a[0]), "r"(a[1]), "r"(a[2]), "r"(a[3]), "r"(b[0]), "r"(b[1]));
}

// ------------------------------ GEMM kernel --------------------------------
// 128 threads, 4 warps 2x2, warp tile 64x64, BK=64, 3-stage cp.async,
// fragment double-buffering (R8 schedule), rotating stage pointers.
// MODE 0: Cf = acc + bias
// MODE 1: Ch = half(acc + bias + temb[m>>3])
// MODE 2: Ch = half(acc + bias)
template<int MODE>
__global__ __launch_bounds__(128, 2)
void gemm_mma(const __half* __restrict__ Ah, const __half* __restrict__ Bh,
              const float* __restrict__ bias, const float* __restrict__ temb,
              float* __restrict__ Cf, __half* __restrict__ Ch,
              int M, int N, int K)
{
    extern __shared__ __align__(128) char smem[];
    const uint32_t sb = smem_u32(smem);

    const int tid  = threadIdx.x;
    const int wid  = tid >> 5;
    const int lane = tid & 31;
    const int warp_m = wid & 1;
    const int warp_n = wid >> 1;
    const int m0 = blockIdx.y * BM;
    const int n0 = blockIdx.x * BN;

    // --- copy addressing: cpc = 16B chunk 0..7, cpr = base row 0..15 ---
    const int cpc = tid & 7;
    const int cpr = tid >> 3;
    const __half* gA = Ah + (size_t)(m0 + cpr) * K + cpc * 8;
    const __half* gB = Bh + (size_t)(n0 + cpr) * K + cpc * 8;
    const size_t rowstep = (size_t)16 * K;
    const uint32_t swz = cpr * 128 + ((cpc ^ (cpr & 7)) << 4);

    float acc[4][8][4];
#pragma unroll
    for (int a = 0; a < 4; a++)
#pragma unroll
        for (int b = 0; b < 8; b++)
#pragma unroll
            for (int c = 0; c < 4; c++) acc[a][b][c] = 0.0f;

    const int KT = K / BK;

    // --- ldmatrix base offsets (XOR-folded): addr = base[f] ^ (ks<<5) ---
    const int lr = lane & 15;
    const int lc = lane >> 4;
    uint32_t aBase[4], bBase[4];
#pragma unroll
    for (int f = 0; f < 4; f++) {
        const int ra = warp_m * 64 + f * 16 + lr;
        const int rb = warp_n * 64 + f * 16 + lr;
        aBase[f] = ra * 128 + ((((ra & 7) ^ lc)) << 4);
        bBase[f] = A_BYTES + rb * 128 + ((((rb & 7) ^ lc)) << 4);
    }

    // --- prologue: stages 0,1 ---
#pragma unroll
    for (int s = 0; s < 2; s++) {
        const uint32_t st = sb + s * STAGE_BYTES;
        const size_t k0 = (size_t)s * BK;
#pragma unroll
        for (int j = 0; j < 8; j++) {
            cp16(st + swz + j * 2048, gA + j * rowstep + k0);
            cp16(st + A_BYTES + swz + j * 2048, gB + j * rowstep + k0);
        }
        CP_COMMIT();
    }
    CP_WAIT1();
    __syncthreads();

    uint32_t aF[2][4][4], bF[2][8][2];

    // preload (kt=0, ks=0) into buf0
#pragma unroll
    for (int p = 0; p < 4; p++) {
        uint32_t r0, r1, r2, r3;
        ldsm_x4(r0, r1, r2, r3, sb + bBase[p]);
        bF[0][2 * p][0] = r0; bF[0][2 * p][1] = r2;
        bF[0][2 * p + 1][0] = r1; bF[0][2 * p + 1][1] = r3;
    }
#pragma unroll
    for (int mf = 0; mf < 4; mf++)
        ldsm_x4(aF[0][mf][0], aF[0][mf][1], aF[0][mf][2], aF[0][mf][3],
                sb + aBase[mf]);

    // rotating stage pointers: cur (kt), nxt (kt+1), tgt (copy dest, kt+2)
    uint32_t stCur = sb;
    uint32_t stNxt = sb + STAGE_BYTES;
    uint32_t stTgt = sb + 2 * STAGE_BYTES;

#pragma unroll 1
    for (int kt = 0; kt < KT; kt++) {
        if (kt + 2 < KT) {
            const size_t k2 = (size_t)(kt + 2) * BK;
#pragma unroll
            for (int j = 0; j < 8; j++) {
                cp16(stTgt + swz + j * 2048, gA + j * rowstep + k2);
                cp16(stTgt + A_BYTES + swz + j * 2048, gB + j * rowstep + k2);
            }
        }
        CP_COMMIT();

#pragma unroll
        for (int ks = 0; ks < 4; ks++) {
            const int cur = ks & 1;
            const int nxt = cur ^ 1;
            if (ks < 3) {
                const uint32_t x = (uint32_t)(ks + 1) << 5;
#pragma unroll
                for (int p = 0; p < 4; p++) {
                    uint32_t r0, r1, r2, r3;
                    ldsm_x4(r0, r1, r2, r3, stCur + (bBase[p] ^ x));
                    bF[nxt][2 * p][0] = r0; bF[nxt][2 * p][1] = r2;
                    bF[nxt][2 * p + 1][0] = r1; bF[nxt][2 * p + 1][1] = r3;
                }
#pragma unroll
                for (int mf = 0; mf < 4; mf++)
                    ldsm_x4(aF[nxt][mf][0], aF[nxt][mf][1],
                            aF[nxt][mf][2], aF[nxt][mf][3],
                            stCur + (aBase[mf] ^ x));
            } else if (kt < KT - 1) {
                CP_WAIT1();
                __syncthreads();
#pragma unroll
                for (int p = 0; p < 4; p++) {
                    uint32_t r0, r1, r2, r3;
                    ldsm_x4(r0, r1, r2, r3, stNxt + bBase[p]);
                    bF[nxt][2 * p][0] = r0; bF[nxt][2 * p][1] = r2;
                    bF[nxt][2 * p + 1][0] = r1; bF[nxt][2 * p + 1][1] = r3;
                }
#pragma unroll
                for (int mf = 0; mf < 4; mf++)
                    ldsm_x4(aF[nxt][mf][0], aF[nxt][mf][1],
                            aF[nxt][mf][2], aF[nxt][mf][3], stNxt + aBase[mf]);
            }
#pragma unroll
            for (int mf = 0; mf < 4; mf++)
#pragma unroll
                for (int nf = 0; nf < 8; nf++)
                    mma16816(acc[mf][nf], aF[cur][mf], bF[cur][nf]);
        }

        // rotate stage pointers (3 MOVs, no modulo)
        const uint32_t tmp = stCur;
        stCur = stNxt;
        stNxt = stTgt;
        stTgt = tmp;
    }

    // ------------------------------- epilogue ------------------------------
#pragma unroll
    for (int mf = 0; mf < 4; mf++)
#pragma unroll
        for (int nf = 0; nf < 8; nf++) {
            const int m = m0 + warp_m * 64 + mf * 16 + (lane >> 2);
            const int n = n0 + warp_n * 64 + nf * 8 + 2 * (lane & 3);
            const float* a = acc[mf][nf];
            const float b0 = bias[n], b1 = bias[n + 1];
            if (MODE == 0) {
                float2 v0 = make_float2(a[0] + b0, a[1] + b1);
                float2 v1 = make_float2(a[2] + b0, a[3] + b1);
                *reinterpret_cast<float2*>(Cf + (size_t)m * N + n) = v0;
                *reinterpret_cast<float2*>(Cf + (size_t)(m + 8) * N + n) = v1;
            } else if (MODE == 1) {
#pragma unroll
                for (int rr = 0; rr < 2; rr++) {
                    const int mm = m + rr * 8;
                    const float* tp = temb + (size_t)(mm >> 3) * OUT_CH + n;
                    const float v0 = a[rr * 2 + 0] + b0 + tp[0];
                    const float v1 = a[rr * 2 + 1] + b1 + tp[1];
                    *reinterpret_cast<__half2*>(Ch + (size_t)mm * N + n) =
                        __floats2half2_rn(v0, v1);
                }
            } else {
                *reinterpret_cast<__half2*>(Ch + (size_t)m * N + n) =
                    __floats2half2_rn(a[0] + b0, a[1] + b1);
                *reinterpret_cast<__half2*>(Ch + (size_t)(m + 8) * N + n) =
                    __floats2half2_rn(a[2] + b0, a[3] + b1);
            }
        }
}

// --------------------------- conversions (one launch) ----------------------
__device__ __forceinline__ void cvt4s(const float* __restrict__ s,
                                      __half* __restrict__ h, int i)
{
    float4 v = *reinterpret_cast<const float4*>(s + i);
    __half2 a = __floats2half2_rn(v.x, v.y);
    __half2 b = __floats2half2_rn(v.z, v.w);
    *reinterpret_cast<uint2*>(h + i) =
        make_uint2(*reinterpret_cast<uint32_t*>(&a), *reinterpret_cast<uint32_t*>(&b));
}

static constexpr int SZ_X  = N_ROWS * IN_CH;
static constexpr int SZ_T  = N_BATCH * T_DIM;
static constexpr int SZ_WD = OUT_CH * IN_CH;
static constexpr int SZ_WT = OUT_CH * T_DIM;
static constexpr int SZ_WQ = QKV_CH * OUT_CH;
static constexpr int SZ_WO = OUT_CH * OUT_CH;
static constexpr int C0 = SZ_X,       C1 = C0 + SZ_T,  C2 = C1 + SZ_WD;
static constexpr int C3 = C2 + SZ_WT, C4 = C3 + SZ_WQ, C5 = C4 + SZ_WO;
static constexpr int CVT_BLOCKS = C5 / 4 / 256;

__global__ __launch_bounds__(256)
void cvt_all(const float* __restrict__ x,  const float* __restrict__ t,
             const float* __restrict__ Wd, const float* __restrict__ Wt,
             const float* __restrict__ Wq, const float* __restrict__ Wo,
             __half* __restrict__ xh,  __half* __restrict__ th,
             __half* __restrict__ Wdh, __half* __restrict__ Wth,
             __half* __restrict__ Wqh, __half* __restrict__ Woh)
{
    int i = (blockIdx.x * 256 + threadIdx.x) * 4;
    if (i < C0)      cvt4s(x,  xh,  i);
    else if (i < C1) cvt4s(t,  th,  i - C0);
    else if (i < C2) cvt4s(Wd, Wdh, i - C1);
    else if (i < C3) cvt4s(Wt, Wth, i - C2);
    else if (i < C4) cvt4s(Wq, Wqh, i - C3);
    else             cvt4s(Wo, Woh, i - C4);
}

// ------------------------------ attention ----------------------------------
__device__ __forceinline__ void unpack8(float* f, uint4 u) {
    const __half2* h = reinterpret_cast<const __half2*>(&u);
#pragma unroll
    for (int k = 0; k < 4; k++) {
        float2 v = __half22float2(h[k]);
        f[2 * k] = v.x; f[2 * k + 1] = v.y;
    }
}

__global__ __launch_bounds__(256)
void attn_kernel(const __half* __restrict__ qkv, __half* __restrict__ oh)
{
    __shared__ __half s[8 * 1728];
    const int tid = threadIdx.x;
    const size_t row0 = (size_t)blockIdx.x * 8;

    const uint4* src = reinterpret_cast<const uint4*>(qkv + row0 * QKV_CH);
    uint4* dst = reinterpret_cast<uint4*>(s);
#pragma unroll
    for (int it = 0; it < 6; it++) {
        int idx = tid + it * 256;
        int r = idx / 192, j = idx - r * 192;
        int grp = j >> 3, w8 = j & 7;
        dst[r * 216 + grp * 9 + w8] = src[idx];
    }
    __syncthreads();

    const int warp = tid >> 5;
    const int lane = tid & 31;
    const __half* qs = s + warp * 1728;
    const int i  = lane & 7;
    const int c0 = (lane >> 3) * 16;

    float qreg[16];
    {
        const __half* qp = qs + i * 72 + c0;
        unpack8(qreg,     *reinterpret_cast<const uint4*>(qp));
        unpack8(qreg + 8, *reinterpret_cast<const uint4*>(qp + 8));
    }

    float w[8];
#pragma unroll
    for (int j = 0; j < 8; j++) {
        const __half* kp = qs + (8 + j) * 72 + c0;
        float kr[16];
        unpack8(kr,     *reinterpret_cast<const uint4*>(kp));
        unpack8(kr + 8, *reinterpret_cast<const uint4*>(kp + 8));
        float acc = 0.0f;
#pragma unroll
        for (int c = 0; c < 16; c++) acc = fmaf(qreg[c], kr[c], acc);
        acc += __shfl_xor_sync(0xffffffffu, acc, 8);
        acc += __shfl_xor_sync(0xffffffffu, acc, 16);
        w[j] = acc * 0.125f;
    }

    float mx = w[0];
#pragma unroll
    for (int j = 1; j < 8; j++) mx = fmaxf(mx, w[j]);
    float sum = 0.0f;
#pragma unroll
    for (int j = 0; j < 8; j++) { w[j] = __expf(w[j] - mx); sum += w[j]; }
    const float inv = 1.0f / sum;

    float o[16];
#pragma unroll
    for (int c = 0; c < 16; c++) o[c] = 0.0f;
#pragma unroll
    for (int j = 0; j < 8; j++) {
        const __half* vp = qs + (16 + j) * 72 + c0;
        float vr[16];
        unpack8(vr,     *reinterpret_cast<const uint4*>(vp));
        unpack8(vr + 8, *reinterpret_cast<const uint4*>(vp + 8));
        const float wj = w[j];
#pragma unroll
        for (int c = 0; c < 16; c++) o[c] = fmaf(wj, vr[c], o[c]);
    }

    __half* op = oh + (row0 + warp) * (size_t)OUT_CH + i * 64 + c0;
    uint32_t pk[8];
#pragma unroll
    for (int p = 0; p < 8; p++) {
        __half2 h = __floats2half2_rn(o[2 * p] * inv, o[2 * p + 1] * inv);
        pk[p] = *reinterpret_cast<uint32_t*>(&h);
    }
    *reinterpret_cast<uint4*>(op)     = make_uint4(pk[0], pk[1], pk[2], pk[3]);
    *reinterpret_cast<uint4*>(op + 8) = make_uint4(pk[4], pk[5], pk[6], pk[7]);
}

// ---------------------------------------------------------------------------
extern "C" void kernel_launch(void* const* d_in, const int* in_sizes, int n_in,
                              void* d_out, int out_size)
{
    const float* x      = (const float*)d_in[0];
    const float* t      = (const float*)d_in[1];
    const float* W_down = (const float*)d_in[2];
    const float* b_down = (const float*)d_in[3];
    const float* W_t    = (const float*)d_in[4];
    const float* b_t    = (const float*)d_in[5];
    const float* W_qkv  = (const float*)d_in[6];
    const float* b_qkv  = (const float*)d_in[7];
    const float* W_out  = (const float*)d_in[8];
    const float* b_out  = (const float*)d_in[9];
    float* out = (float*)d_out;

    __half *xh, *th, *Wdh, *Wth, *Wqh, *Woh, *yh, *qkvh, *ath;
    float *temb;
    cudaGetSymbolAddress((void**)&xh,   g_xh);
    cudaGetSymbolAddress((void**)&th,   g_th);
    cudaGetSymbolAddress((void**)&Wdh,  g_Wdh);
    cudaGetSymbolAddress((void**)&Wth,  g_Wth);
    cudaGetSymbolAddress((void**)&Wqh,  g_Wqh);
    cudaGetSymbolAddress((void**)&Woh,  g_Woh);
    cudaGetSymbolAddress((void**)&temb, g_temb);
    cudaGetSymbolAddress((void**)&yh,   g_yh);
    cudaGetSymbolAddress((void**)&qkvh, g_qkvh);
    cudaGetSymbolAddress((void**)&ath,  g_ath);

    cudaFuncSetAttribute(gemm_mma<0>, cudaFuncAttributeMaxDynamicSharedMemorySize, SMEM_BYTES);
    cudaFuncSetAttribute(gemm_mma<1>, cudaFuncAttributeMaxDynamicSharedMemorySize, SMEM_BYTES);
    cudaFuncSetAttribute(gemm_mma<2>, cudaFuncAttributeMaxDynamicSharedMemorySize, SMEM_BYTES);

    // launch 0: conversions
    cvt_all<<<CVT_BLOCKS, 256>>>(x, t, W_down, W_t, W_qkv, W_out,
                                 xh, th, Wdh, Wth, Wqh, Woh);

    // launch 1: temb = t @ W_t^T + b_t             [8192, 512] fp32
    gemm_mma<0><<<dim3(OUT_CH / BN, N_BATCH / BM), 128, SMEM_BYTES>>>(
        th, Wth, b_t, nullptr, temb, nullptr, N_BATCH, OUT_CH, T_DIM);

    // launch 2: y = x @ W_down^T + b_down + temb   -> fp16
    gemm_mma<1><<<dim3(OUT_CH / BN, N_ROWS / BM), 128, SMEM_BYTES>>>(
        xh, Wdh, b_down, temb, nullptr, yh, N_ROWS, OUT_CH, IN_CH);

    // launch 3: qkv = y @ W_qkv^T + b_qkv          -> fp16
    gemm_mma<2><<<dim3(QKV_CH / BN, N_ROWS / BM), 128, SMEM_BYTES>>>(
        yh, Wqh, b_qkv, nullptr, nullptr, qkvh, N_ROWS, QKV_CH, OUT_CH);

    // launch 4: att = rowwise attention(qkv)       -> fp16
    attn_kernel<<<N_ROWS / 8, 256>>>(qkvh, ath);

    // launch 5 (ncu capture target): out = att @ W_out^T + b_out (fp32)
    gemm_mma<0><<<dim3(OUT_CH / BN, N_ROWS / BM), 128, SMEM_BYTES>>>(
        ath, Woh, b_out, nullptr, out, nullptr, N_ROWS, OUT_CH, OUT_CH);
}